// round 1
// baseline (speedup 1.0000x reference)
#include <cuda_runtime.h>
#include <cstddef>

#define N_NODES   100000
#define N_EDGES   3200000
#define N_GRAPHS  64
#define N_CLASSES 10

// ---------------------------------------------------------------------------
// Static device scratch (no allocation allowed)
// ---------------------------------------------------------------------------
__device__ float g_bufA[(size_t)N_NODES * 512];    // 204.8 MB
__device__ float g_bufB[(size_t)N_NODES * 1024];   // 409.6 MB
__device__ int   g_in_deg[N_NODES];
__device__ int   g_out_deg[N_NODES];
__device__ float g_in_inv[N_NODES];
__device__ float g_out_inv[N_NODES];
__device__ int   g_row_off[N_NODES + 1];
__device__ int   g_cursor[N_NODES];
__device__ int   g_csr_src[N_EDGES];
__device__ float g_pool[N_GRAPHS * 32];
__device__ float g_cnt[N_GRAPHS];

// ---------------------------------------------------------------------------
// Preprocessing kernels
// ---------------------------------------------------------------------------
__global__ void init_zero_kernel() {
    int i = blockIdx.x * blockDim.x + threadIdx.x;
    if (i < N_NODES) { g_in_deg[i] = 0; g_out_deg[i] = 0; g_cursor[i] = 0; }
    if (i < N_GRAPHS * 32) g_pool[i] = 0.0f;
    if (i < N_GRAPHS) g_cnt[i] = 0.0f;
}

__global__ void degree_kernel(const int* __restrict__ src, const int* __restrict__ dst) {
    int e = blockIdx.x * blockDim.x + threadIdx.x;
    if (e < N_EDGES) {
        atomicAdd(&g_out_deg[src[e]], 1);
        atomicAdd(&g_in_deg[dst[e]], 1);
    }
}

__global__ void inv_kernel() {
    int i = blockIdx.x * blockDim.x + threadIdx.x;
    if (i < N_NODES) {
        g_out_inv[i] = rsqrtf(fmaxf((float)g_out_deg[i], 1.0f));
        g_in_inv[i]  = rsqrtf(fmaxf((float)g_in_deg[i], 1.0f));
    }
}

// Single-block exclusive scan of in-degrees -> CSR row offsets.
__global__ void scan_kernel() {
    __shared__ int temp[1024];
    __shared__ int carry_s;
    int tid = threadIdx.x;
    if (tid == 0) carry_s = 0;
    __syncthreads();
    for (int base = 0; base < N_NODES; base += 1024) {
        int i = base + tid;
        int v = (i < N_NODES) ? g_in_deg[i] : 0;
        temp[tid] = v;
        __syncthreads();
        for (int off = 1; off < 1024; off <<= 1) {
            int t = (tid >= off) ? temp[tid - off] : 0;
            __syncthreads();
            temp[tid] += t;
            __syncthreads();
        }
        int incl = temp[tid];
        int c = carry_s;
        if (i < N_NODES) g_row_off[i] = c + incl - v;
        __syncthreads();
        if (tid == 1023) carry_s = c + incl;
        __syncthreads();
    }
    if (tid == 0) g_row_off[N_NODES] = carry_s;
}

__global__ void bin_kernel(const int* __restrict__ src, const int* __restrict__ dst) {
    int e = blockIdx.x * blockDim.x + threadIdx.x;
    if (e < N_EDGES) {
        int d = dst[e];
        int pos = g_row_off[d] + atomicAdd(&g_cursor[d], 1);
        g_csr_src[pos] = src[e];
    }
}

// ---------------------------------------------------------------------------
// SpMM: Y[n] = in_inv[n] * sum_{s in N(n)} out_inv[s] * X[s]   (+bias, relu)
// ---------------------------------------------------------------------------
template <int D, bool EPI>
__global__ void spmm_kernel(const float* __restrict__ X, float* __restrict__ Y,
                            const float* __restrict__ bias) {
    constexpr int TPN = (D < 256) ? D : 256;   // threads per node
    constexpr int NPB = 256 / TPN;             // nodes per block
    constexpr int FPT = D / TPN;               // features per thread

    int node = blockIdx.x * NPB + threadIdx.x / TPN;
    if (node >= N_NODES) return;
    int f = threadIdx.x % TPN;

    float acc[FPT];
#pragma unroll
    for (int i = 0; i < FPT; i++) acc[i] = 0.0f;

    int s0 = g_row_off[node];
    int s1 = g_row_off[node + 1];
    for (int j = s0; j < s1; j++) {
        int s = g_csr_src[j];
        float w = g_out_inv[s];
        const float* xr = X + (size_t)s * D + f;
#pragma unroll
        for (int i = 0; i < FPT; i++) acc[i] += w * xr[i * TPN];
    }
    float win = g_in_inv[node];
    float* yr = Y + (size_t)node * D + f;
#pragma unroll
    for (int i = 0; i < FPT; i++) {
        float v = acc[i] * win;
        if (EPI) {
            v += bias[f + i * TPN];
            v = fmaxf(v, 0.0f);
        }
        yr[i * TPN] = v;
    }
}

// ---------------------------------------------------------------------------
// GEMM: C[M,N] = A[M,K] @ B[K,N]  (+bias, relu)   64x64 tile, BK=16, 256 thr
// ---------------------------------------------------------------------------
template <bool EPI>
__global__ void gemm_kernel(const float* __restrict__ A, const float* __restrict__ B,
                            const float* __restrict__ bias, float* __restrict__ C,
                            int M, int K, int N) {
    __shared__ float As[16][64];   // As[k][m]
    __shared__ float Bs[16][64];   // Bs[k][n]

    int tid = threadIdx.x;
    int tx = tid % 16, ty = tid / 16;
    int block_m = blockIdx.y * 64;
    int block_n = blockIdx.x * 64;

    int ar = tid / 4;            // 0..63 : m-row within tile
    int ak = (tid % 4) * 4;      // 0,4,8,12 : k offset (float4)
    int br = tid / 16;           // 0..15 : k-row
    int bn = (tid % 16) * 4;     // 0..60 : n offset (float4)

    float acc[4][4];
#pragma unroll
    for (int i = 0; i < 4; i++)
#pragma unroll
        for (int j = 0; j < 4; j++) acc[i][j] = 0.0f;

    for (int k0 = 0; k0 < K; k0 += 16) {
        // load A tile (transposed into As[k][m])
        float4 av = make_float4(0.f, 0.f, 0.f, 0.f);
        int gm = block_m + ar;
        if (gm < M) av = *(const float4*)(A + (size_t)gm * K + k0 + ak);
        As[ak + 0][ar] = av.x;
        As[ak + 1][ar] = av.y;
        As[ak + 2][ar] = av.z;
        As[ak + 3][ar] = av.w;

        // load B tile
        float4 bv = make_float4(0.f, 0.f, 0.f, 0.f);
        int gk = k0 + br;
        int gn = block_n + bn;
        if (gn + 3 < N) {
            bv = *(const float4*)(B + (size_t)gk * N + gn);
        } else {
            if (gn + 0 < N) bv.x = B[(size_t)gk * N + gn + 0];
            if (gn + 1 < N) bv.y = B[(size_t)gk * N + gn + 1];
            if (gn + 2 < N) bv.z = B[(size_t)gk * N + gn + 2];
            if (gn + 3 < N) bv.w = B[(size_t)gk * N + gn + 3];
        }
        *(float4*)&Bs[br][bn] = bv;

        __syncthreads();

#pragma unroll
        for (int k = 0; k < 16; k++) {
            float4 ra = *(const float4*)&As[k][ty * 4];
            float4 rb = *(const float4*)&Bs[k][tx * 4];
            float a_[4] = {ra.x, ra.y, ra.z, ra.w};
            float b_[4] = {rb.x, rb.y, rb.z, rb.w};
#pragma unroll
            for (int i = 0; i < 4; i++)
#pragma unroll
                for (int j = 0; j < 4; j++) acc[i][j] += a_[i] * b_[j];
        }
        __syncthreads();
    }

#pragma unroll
    for (int i = 0; i < 4; i++) {
        int gm = block_m + ty * 4 + i;
        if (gm >= M) continue;
#pragma unroll
        for (int j = 0; j < 4; j++) {
            int gn = block_n + tx * 4 + j;
            if (gn >= N) continue;
            float v = acc[i][j];
            if (EPI) {
                v += bias[gn];
                v = fmaxf(v, 0.0f);
            }
            C[(size_t)gm * N + gn] = v;
        }
    }
}

// ---------------------------------------------------------------------------
// Pooling + classifier
// ---------------------------------------------------------------------------
__global__ void pool_kernel(const float* __restrict__ H, const int* __restrict__ gid) {
    int i = blockIdx.x * blockDim.x + threadIdx.x;
    if (i < N_NODES * 32) {
        int n = i >> 5, f = i & 31;
        atomicAdd(&g_pool[gid[n] * 32 + f], H[i]);
    }
}

__global__ void count_kernel(const int* __restrict__ gid) {
    int n = blockIdx.x * blockDim.x + threadIdx.x;
    if (n < N_NODES) atomicAdd(&g_cnt[gid[n]], 1.0f);
}

__global__ void classify_kernel(const float* __restrict__ Wc, const float* __restrict__ bc,
                                float* __restrict__ out) {
    int i = threadIdx.x;
    if (i < N_GRAPHS * N_CLASSES) {
        int g = i / N_CLASSES, c = i % N_CLASSES;
        float inv_cnt = 1.0f / fmaxf(g_cnt[g], 1.0f);
        float s = 0.0f;
#pragma unroll
        for (int k = 0; k < 32; k++)
            s += (g_pool[g * 32 + k] * inv_cnt) * Wc[k * N_CLASSES + c];
        out[i] = s + bc[c];
    }
}

// ---------------------------------------------------------------------------
// Launch
// ---------------------------------------------------------------------------
extern "C" void kernel_launch(void* const* d_in, const int* in_sizes, int n_in,
                              void* d_out, int out_size) {
    const float* h   = (const float*)d_in[0];
    const int*   src = (const int*)d_in[1];
    const int*   dst = (const int*)d_in[2];
    const int*   gid = (const int*)d_in[3];
    const float* W[6];
    const float* b[6];
    for (int i = 0; i < 6; i++) {
        W[i] = (const float*)d_in[4 + 2 * i];
        b[i] = (const float*)d_in[5 + 2 * i];
    }
    const float* Wc = (const float*)d_in[16];
    const float* bc = (const float*)d_in[17];
    float* out = (float*)d_out;

    float *bufA, *bufB;
    cudaGetSymbolAddress((void**)&bufA, g_bufA);
    cudaGetSymbolAddress((void**)&bufB, g_bufB);

    const int M = N_NODES;

    // Graph preprocessing
    init_zero_kernel<<<(N_NODES + 255) / 256, 256>>>();
    degree_kernel<<<(N_EDGES + 255) / 256, 256>>>(src, dst);
    inv_kernel<<<(N_NODES + 255) / 256, 256>>>();
    scan_kernel<<<1, 1024>>>();
    bin_kernel<<<(N_EDGES + 255) / 256, 256>>>(src, dst);

    // Layer 1: 512 -> 1024 (fi <= fo: SpMM first, then GEMM + bias + relu)
    spmm_kernel<512, false><<<N_NODES, 256>>>(h, bufA, nullptr);
    gemm_kernel<true><<<dim3(1024 / 64, (M + 63) / 64), 256>>>(bufA, W[0], b[0], bufB, M, 512, 1024);

    // Layer 2: 1024 -> 512 (fi > fo: GEMM first, SpMM + bias + relu)
    gemm_kernel<false><<<dim3(512 / 64, (M + 63) / 64), 256>>>(bufB, W[1], nullptr, bufA, M, 1024, 512);
    spmm_kernel<512, true><<<N_NODES, 256>>>(bufA, bufB, b[1]);

    // Layer 3: 512 -> 256
    gemm_kernel<false><<<dim3(256 / 64, (M + 63) / 64), 256>>>(bufB, W[2], nullptr, bufA, M, 512, 256);
    spmm_kernel<256, true><<<N_NODES, 256>>>(bufA, bufB, b[2]);

    // Layer 4: 256 -> 128
    gemm_kernel<false><<<dim3(128 / 64, (M + 63) / 64), 256>>>(bufB, W[3], nullptr, bufA, M, 256, 128);
    spmm_kernel<128, true><<<(N_NODES + 1) / 2, 256>>>(bufA, bufB, b[3]);

    // Layer 5: 128 -> 64
    gemm_kernel<false><<<dim3(64 / 64, (M + 63) / 64), 256>>>(bufB, W[4], nullptr, bufA, M, 128, 64);
    spmm_kernel<64, true><<<(N_NODES + 3) / 4, 256>>>(bufA, bufB, b[4]);

    // Layer 6: 64 -> 32
    gemm_kernel<false><<<dim3(1, (M + 63) / 64), 256>>>(bufB, W[5], nullptr, bufA, M, 64, 32);
    spmm_kernel<32, true><<<(N_NODES + 7) / 8, 256>>>(bufA, bufB, b[5]);

    // Mean pooling + classifier
    pool_kernel<<<(N_NODES * 32 + 255) / 256, 256>>>(bufB, gid);
    count_kernel<<<(N_NODES + 255) / 256, 256>>>(gid);
    classify_kernel<<<1, 640>>>(Wc, bc, out);
}

// round 3
// speedup vs baseline: 2.0977x; 2.0977x over previous
#include <cuda_runtime.h>
#include <cstddef>
#include <cstdint>

#define N_NODES   100000
#define N_EDGES   3200000
#define N_GRAPHS  64
#define N_CLASSES 10

// ---------------------------------------------------------------------------
// Static device scratch (no allocation allowed)
// ---------------------------------------------------------------------------
__device__ float g_bufA[(size_t)N_NODES * 512];    // 204.8 MB
__device__ float g_bufB[(size_t)N_NODES * 1024];   // 409.6 MB
__device__ float g_wt[1222656];                    // transposed (tf32-rounded) weights
__device__ int   g_in_deg[N_NODES];
__device__ int   g_out_deg[N_NODES];
__device__ float g_in_inv[N_NODES];
__device__ float g_out_inv[N_NODES];
__device__ int   g_row_off[N_NODES + 1];
__device__ int   g_cursor[N_NODES];
__device__ int   g_csr_src[N_EDGES];
__device__ int   g_blocksum[128];
__device__ int   g_blockoff[128];
__device__ float g_pool[N_GRAPHS * 32];
__device__ float g_cnt[N_GRAPHS];

// ---------------------------------------------------------------------------
// Family-portable helpers (sm_80-era: cp.async + mma.sync tf32)
// ---------------------------------------------------------------------------
__device__ __forceinline__ void cp16(uint32_t dst, const void* src, bool valid) {
    asm volatile("cp.async.cg.shared.global [%0], [%1], 16, %2;"
                 :: "r"(dst), "l"(src), "r"(valid ? 16 : 0));
}
#define CP_COMMIT() asm volatile("cp.async.commit_group;" ::: "memory")
#define CP_WAIT(n)  asm volatile("cp.async.wait_group %0;" :: "n"(n) : "memory")

__device__ __forceinline__ float to_tf32(float x) {
    float y;
    asm("cvt.rna.tf32.f32 %0, %1;" : "=f"(y) : "f"(x));
    return y;
}

__device__ __forceinline__ void mma_tf32(float* d, const uint32_t* a,
                                         uint32_t b0, uint32_t b1) {
    asm volatile(
        "mma.sync.aligned.m16n8k8.row.col.f32.tf32.tf32.f32 "
        "{%0,%1,%2,%3}, {%4,%5,%6,%7}, {%8,%9}, {%0,%1,%2,%3};"
        : "+f"(d[0]), "+f"(d[1]), "+f"(d[2]), "+f"(d[3])
        : "r"(a[0]), "r"(a[1]), "r"(a[2]), "r"(a[3]), "r"(b0), "r"(b1));
}

// ---------------------------------------------------------------------------
// Preprocessing
// ---------------------------------------------------------------------------
__global__ void init_zero_kernel() {
    int i = blockIdx.x * blockDim.x + threadIdx.x;
    if (i < N_NODES) { g_in_deg[i] = 0; g_out_deg[i] = 0; g_cursor[i] = 0; }
    if (i < N_GRAPHS * 32) g_pool[i] = 0.0f;
    if (i < N_GRAPHS) g_cnt[i] = 0.0f;
}

__global__ void degree_kernel(const int* __restrict__ src, const int* __restrict__ dst) {
    int e = blockIdx.x * blockDim.x + threadIdx.x;
    if (e < N_EDGES) {
        atomicAdd(&g_out_deg[src[e]], 1);
        atomicAdd(&g_in_deg[dst[e]], 1);
    }
}

__global__ void inv_kernel() {
    int i = blockIdx.x * blockDim.x + threadIdx.x;
    if (i < N_NODES) {
        g_out_inv[i] = rsqrtf(fmaxf((float)g_out_deg[i], 1.0f));
        g_in_inv[i]  = rsqrtf(fmaxf((float)g_in_deg[i], 1.0f));
    }
}

#define SCAN_BLK 98
__global__ void scan_pass1() {
    __shared__ int temp[1024];
    int tid = threadIdx.x;
    int i = blockIdx.x * 1024 + tid;
    int v = (i < N_NODES) ? g_in_deg[i] : 0;
    temp[tid] = v;
    __syncthreads();
    for (int off = 1; off < 1024; off <<= 1) {
        int t = (tid >= off) ? temp[tid - off] : 0;
        __syncthreads();
        temp[tid] += t;
        __syncthreads();
    }
    if (i < N_NODES) g_row_off[i] = temp[tid] - v;
    if (tid == 1023) g_blocksum[blockIdx.x] = temp[1023];
}

__global__ void scan_pass2() {
    __shared__ int s[SCAN_BLK];
    int tid = threadIdx.x;
    if (tid < SCAN_BLK) s[tid] = g_blocksum[tid];
    __syncthreads();
    if (tid == 0) {
        int acc = 0;
        for (int b = 0; b < SCAN_BLK; b++) { int t = s[b]; s[b] = acc; acc += t; }
        g_row_off[N_NODES] = acc;
    }
    __syncthreads();
    if (tid < SCAN_BLK) g_blockoff[tid] = s[tid];
}

__global__ void scan_pass3() {
    int i = blockIdx.x * 1024 + threadIdx.x;
    if (i < N_NODES) g_row_off[i] += g_blockoff[blockIdx.x];
}

__global__ void bin_kernel(const int* __restrict__ src, const int* __restrict__ dst) {
    int e = blockIdx.x * blockDim.x + threadIdx.x;
    if (e < N_EDGES) {
        int d = dst[e];
        int pos = g_row_off[d] + atomicAdd(&g_cursor[d], 1);
        g_csr_src[pos] = src[e];
    }
}

// W[k][n] -> Wt[n][k], rounded to tf32
__global__ void transpose_kernel(const float* __restrict__ W, float* __restrict__ Wt,
                                 int K, int N) {
    int i = blockIdx.x * blockDim.x + threadIdx.x;
    if (i < K * N) {
        int k = i / N, n = i % N;
        Wt[(size_t)n * K + k] = to_tf32(W[i]);
    }
}

// ---------------------------------------------------------------------------
// SpMM: Y[n] = in_inv[n] * sum_{s in N(n)} out_inv[s] * X[s]   (+bias, relu)
// CVT: round output to tf32 (it feeds a GEMM A-operand next)
// ---------------------------------------------------------------------------
template <int D, bool EPI, bool CVT>
__global__ void spmm_kernel(const float* __restrict__ X, float* __restrict__ Y,
                            const float* __restrict__ bias) {
    constexpr int TPN = (D < 256) ? D : 256;
    constexpr int NPB = 256 / TPN;
    constexpr int FPT = D / TPN;

    int node = blockIdx.x * NPB + threadIdx.x / TPN;
    if (node >= N_NODES) return;
    int f = threadIdx.x % TPN;

    float acc[FPT];
#pragma unroll
    for (int i = 0; i < FPT; i++) acc[i] = 0.0f;

    int s0 = g_row_off[node];
    int s1 = g_row_off[node + 1];
    for (int j = s0; j < s1; j++) {
        int s = g_csr_src[j];
        float w = g_out_inv[s];
        const float* xr = X + (size_t)s * D + f;
#pragma unroll
        for (int i = 0; i < FPT; i++) acc[i] += w * xr[i * TPN];
    }
    float win = g_in_inv[node];
    float* yr = Y + (size_t)node * D + f;
#pragma unroll
    for (int i = 0; i < FPT; i++) {
        float v = acc[i] * win;
        if (EPI) {
            v += bias[f + i * TPN];
            v = fmaxf(v, 0.0f);
        }
        if (CVT) v = to_tf32(v);
        yr[i * TPN] = v;
    }
}

// ---------------------------------------------------------------------------
// tf32 mma.sync GEMM: C[M,N] = A[M,K] @ Bt[N,K]^T  (+bias, relu)
// 128 x BN tile, BK=32, 256 thr (warps 4x2), cp.async double-buffered.
// A and Bt are already tf32-rounded.
// ---------------------------------------------------------------------------
template <int BN, bool EPI>
__global__ void __launch_bounds__(256, 1)
mma_gemm_kernel(const float* __restrict__ A, const float* __restrict__ Bt,
                const float* __restrict__ bias, float* __restrict__ C,
                int M, int K, int N) {
    extern __shared__ float sm[];
    constexpr int LD = 36;                  // padded row (floats), conflict-free frags
    constexpr int A_FLOATS = 128 * LD;
    constexpr int B_FLOATS = BN * LD;
    constexpr int STAGE = A_FLOATS + B_FLOATS;
    constexpr int WN = BN / 2;
    constexpr int NT = WN / 8;              // n-tiles per warp

    int tid = threadIdx.x;
    int lane = tid & 31, w = tid >> 5;
    int wm = w & 3, wn = w >> 2;
    int gid = lane >> 2, tig = lane & 3;
    int block_m = blockIdx.y * 128;
    int block_n = blockIdx.x * BN;

    uint32_t sm_u32 = (uint32_t)__cvta_generic_to_shared(sm);
    const int nChunks = K >> 5;

    auto load_stage = [&](int c, int buf) {
        int k0 = c << 5;
        uint32_t abase = sm_u32 + buf * STAGE * 4;
        uint32_t bbase = abase + A_FLOATS * 4;
        // A: 128 rows x 8 float4
#pragma unroll
        for (int t = 0; t < 4; t++) {
            int idx = tid + t * 256;
            int row = idx >> 3, c4 = idx & 7;
            int gm = block_m + row;
            cp16(abase + (row * LD + c4 * 4) * 4,
                 A + (size_t)gm * K + k0 + c4 * 4, gm < M);
        }
        // B: BN rows x 8 float4
#pragma unroll
        for (int t = 0; t < BN * 8 / 256; t++) {
            int idx = tid + t * 256;
            int row = idx >> 3, c4 = idx & 7;
            cp16(bbase + (row * LD + c4 * 4) * 4,
                 Bt + (size_t)(block_n + row) * K + k0 + c4 * 4, true);
        }
        CP_COMMIT();
    };

    float acc[2][NT][4];
#pragma unroll
    for (int mi = 0; mi < 2; mi++)
#pragma unroll
        for (int ni = 0; ni < NT; ni++)
#pragma unroll
            for (int j = 0; j < 4; j++) acc[mi][ni][j] = 0.0f;

    load_stage(0, 0);

    for (int c = 0; c < nChunks; c++) {
        if (c + 1 < nChunks) {
            load_stage(c + 1, (c + 1) & 1);
            CP_WAIT(1);
        } else {
            CP_WAIT(0);
        }
        __syncthreads();

        const float* AsC = sm + (c & 1) * STAGE;
        const float* BsC = AsC + A_FLOATS;

#pragma unroll
        for (int kk = 0; kk < 4; kk++) {
            uint32_t af[2][4];
#pragma unroll
            for (int mi = 0; mi < 2; mi++) {
                int r0 = wm * 32 + mi * 16 + gid;
                af[mi][0] = __float_as_uint(AsC[r0 * LD + kk * 8 + tig]);
                af[mi][1] = __float_as_uint(AsC[(r0 + 8) * LD + kk * 8 + tig]);
                af[mi][2] = __float_as_uint(AsC[r0 * LD + kk * 8 + tig + 4]);
                af[mi][3] = __float_as_uint(AsC[(r0 + 8) * LD + kk * 8 + tig + 4]);
            }
#pragma unroll
            for (int ni = 0; ni < NT; ni++) {
                int br = wn * WN + ni * 8 + gid;
                uint32_t b0 = __float_as_uint(BsC[br * LD + kk * 8 + tig]);
                uint32_t b1 = __float_as_uint(BsC[br * LD + kk * 8 + tig + 4]);
                mma_tf32(acc[0][ni], af[0], b0, b1);
                mma_tf32(acc[1][ni], af[1], b0, b1);
            }
        }
        __syncthreads();
    }

    // epilogue
#pragma unroll
    for (int mi = 0; mi < 2; mi++) {
        int gm0 = block_m + wm * 32 + mi * 16 + gid;
#pragma unroll
        for (int ni = 0; ni < NT; ni++) {
            int gn = block_n + wn * WN + ni * 8 + 2 * tig;
            float bx = 0.f, by = 0.f;
            if (EPI) { bx = bias[gn]; by = bias[gn + 1]; }
            if (gm0 < M) {
                float2 v;
                v.x = acc[mi][ni][0];
                v.y = acc[mi][ni][1];
                if (EPI) { v.x = fmaxf(v.x + bx, 0.f); v.y = fmaxf(v.y + by, 0.f); }
                *(float2*)(C + (size_t)gm0 * N + gn) = v;
            }
            if (gm0 + 8 < M) {
                float2 v;
                v.x = acc[mi][ni][2];
                v.y = acc[mi][ni][3];
                if (EPI) { v.x = fmaxf(v.x + bx, 0.f); v.y = fmaxf(v.y + by, 0.f); }
                *(float2*)(C + (size_t)(gm0 + 8) * N + gn) = v;
            }
        }
    }
}

// ---------------------------------------------------------------------------
// Pooling + classifier
// ---------------------------------------------------------------------------
__global__ void pool_kernel(const float* __restrict__ H, const int* __restrict__ gid) {
    int i = blockIdx.x * blockDim.x + threadIdx.x;
    if (i < N_NODES * 32) {
        int n = i >> 5, f = i & 31;
        atomicAdd(&g_pool[gid[n] * 32 + f], H[i]);
    }
}

__global__ void count_kernel(const int* __restrict__ gid) {
    int n = blockIdx.x * blockDim.x + threadIdx.x;
    if (n < N_NODES) atomicAdd(&g_cnt[gid[n]], 1.0f);
}

__global__ void classify_kernel(const float* __restrict__ Wc, const float* __restrict__ bc,
                                float* __restrict__ out) {
    int i = threadIdx.x;
    if (i < N_GRAPHS * N_CLASSES) {
        int g = i / N_CLASSES, c = i % N_CLASSES;
        float inv_cnt = 1.0f / fmaxf(g_cnt[g], 1.0f);
        float s = 0.0f;
#pragma unroll
        for (int k = 0; k < 32; k++)
            s += (g_pool[g * 32 + k] * inv_cnt) * Wc[k * N_CLASSES + c];
        out[i] = s + bc[c];
    }
}

// ---------------------------------------------------------------------------
// Launch
// ---------------------------------------------------------------------------
extern "C" void kernel_launch(void* const* d_in, const int* in_sizes, int n_in,
                              void* d_out, int out_size) {
    const float* h   = (const float*)d_in[0];
    const int*   src = (const int*)d_in[1];
    const int*   dst = (const int*)d_in[2];
    const int*   gid = (const int*)d_in[3];
    const float* W[6];
    const float* b[6];
    for (int i = 0; i < 6; i++) {
        W[i] = (const float*)d_in[4 + 2 * i];
        b[i] = (const float*)d_in[5 + 2 * i];
    }
    const float* Wc = (const float*)d_in[16];
    const float* bc = (const float*)d_in[17];
    float* out = (float*)d_out;

    float *bufA, *bufB, *wt;
    cudaGetSymbolAddress((void**)&bufA, g_bufA);
    cudaGetSymbolAddress((void**)&bufB, g_bufB);
    cudaGetSymbolAddress((void**)&wt, g_wt);

    const int M = N_NODES;
    const int dims[7] = {512, 1024, 512, 256, 128, 64, 32};
    size_t wt_off[6];
    {
        size_t acc = 0;
        for (int i = 0; i < 6; i++) { wt_off[i] = acc; acc += (size_t)dims[i] * dims[i + 1]; }
    }

    auto smem_bytes = [](int BN) { return 2 * (128 + BN) * 36 * 4; };
    cudaFuncSetAttribute(mma_gemm_kernel<128, true>,  cudaFuncAttributeMaxDynamicSharedMemorySize, smem_bytes(128));
    cudaFuncSetAttribute(mma_gemm_kernel<128, false>, cudaFuncAttributeMaxDynamicSharedMemorySize, smem_bytes(128));
    cudaFuncSetAttribute(mma_gemm_kernel<64,  false>, cudaFuncAttributeMaxDynamicSharedMemorySize, smem_bytes(64));
    cudaFuncSetAttribute(mma_gemm_kernel<32,  false>, cudaFuncAttributeMaxDynamicSharedMemorySize, smem_bytes(32));

    // Graph preprocessing
    init_zero_kernel<<<(N_NODES + 255) / 256, 256>>>();
    degree_kernel<<<(N_EDGES + 255) / 256, 256>>>(src, dst);
    inv_kernel<<<(N_NODES + 255) / 256, 256>>>();
    scan_pass1<<<SCAN_BLK, 1024>>>();
    scan_pass2<<<1, 128>>>();
    scan_pass3<<<SCAN_BLK, 1024>>>();
    bin_kernel<<<(N_EDGES + 255) / 256, 256>>>(src, dst);

    // Weight transposes (tf32-rounded)
    for (int i = 0; i < 6; i++) {
        int kn = dims[i] * dims[i + 1];
        transpose_kernel<<<(kn + 255) / 256, 256>>>(W[i], wt + wt_off[i], dims[i], dims[i + 1]);
    }

    const int MB = (M + 127) / 128;

    // Layer 1: 512 -> 1024 (SpMM first, GEMM + bias + relu)
    spmm_kernel<512, false, true><<<N_NODES, 256>>>(h, bufA, nullptr);
    mma_gemm_kernel<128, true><<<dim3(1024 / 128, MB), 256, smem_bytes(128)>>>(
        bufA, wt + wt_off[0], b[0], bufB, M, 512, 1024);

    // Layer 2: 1024 -> 512
    mma_gemm_kernel<128, false><<<dim3(512 / 128, MB), 256, smem_bytes(128)>>>(
        bufB, wt + wt_off[1], nullptr, bufA, M, 1024, 512);
    spmm_kernel<512, true, true><<<N_NODES, 256>>>(bufA, bufB, b[1]);

    // Layer 3: 512 -> 256
    mma_gemm_kernel<128, false><<<dim3(256 / 128, MB), 256, smem_bytes(128)>>>(
        bufB, wt + wt_off[2], nullptr, bufA, M, 512, 256);
    spmm_kernel<256, true, true><<<N_NODES, 256>>>(bufA, bufB, b[2]);

    // Layer 4: 256 -> 128
    mma_gemm_kernel<128, false><<<dim3(1, MB), 256, smem_bytes(128)>>>(
        bufB, wt + wt_off[3], nullptr, bufA, M, 256, 128);
    spmm_kernel<128, true, true><<<(N_NODES + 1) / 2, 256>>>(bufA, bufB, b[3]);

    // Layer 5: 128 -> 64
    mma_gemm_kernel<64, false><<<dim3(1, MB), 256, smem_bytes(64)>>>(
        bufB, wt + wt_off[4], nullptr, bufA, M, 128, 64);
    spmm_kernel<64, true, true><<<(N_NODES + 3) / 4, 256>>>(bufA, bufB, b[4]);

    // Layer 6: 64 -> 32 (output feeds pooling: keep full fp32)
    mma_gemm_kernel<32, false><<<dim3(1, MB), 256, smem_bytes(32)>>>(
        bufB, wt + wt_off[5], nullptr, bufA, M, 64, 32);
    spmm_kernel<32, true, false><<<(N_NODES + 7) / 8, 256>>>(bufA, bufB, b[5]);

    // Mean pooling + classifier
    pool_kernel<<<(N_NODES * 32 + 255) / 256, 256>>>(bufB, gid);
    count_kernel<<<(N_NODES + 255) / 256, 256>>>(gid);
    classify_kernel<<<1, 640>>>(Wc, bc, out);
}